// round 10
// baseline (speedup 1.0000x reference)
#include <cuda_runtime.h>
#include <cuda_bf16.h>
#include <cstdint>
#include <math.h>

typedef __nv_bfloat16 bf16;

#define D_DIM 3072
#define H_DIM 1024
#define Z_DIM 32
#define BS    128
#define NN    32
#define RTOT  4096
#define MENC  4224

// GEMM tile: 128 x 128, K-chunk 32, 8 warps (2x4), warp tile 64x32 (proven)
#define SA 40
#define SB 136
#define ASZ (128 * SA * 2)
#define BSZ (32 * SB * 2)
#define STG (ASZ + BSZ)
#define NSTAGE 3
#define SMEM_DYN (NSTAGE * STG)

enum { EPI_BIAS_RELU_BF = 0, EPI_NONE_BF = 1, EPI_LOSS = 2 };

// ------------------------- scratch (no allocation) -------------------------
__device__ __align__(16) bf16  g_Abf [MENC * D_DIM];
__device__ __align__(16) bf16  g_We1b[D_DIM * H_DIM];
__device__ __align__(16) bf16  g_We2b[H_DIM * H_DIM];
__device__ __align__(16) bf16  g_We3b[H_DIM * Z_DIM];
__device__ __align__(16) bf16  g_Wd1b[Z_DIM * H_DIM];
__device__ __align__(16) bf16  g_Wd2b[H_DIM * H_DIM];
__device__ __align__(16) bf16  g_Wd3b[H_DIM * D_DIM];
__device__ __align__(16) bf16  g_H1b [MENC * H_DIM];
__device__ __align__(16) bf16  g_H2b [MENC * H_DIM];
__device__ __align__(16) float g_Z   [MENC * Z_DIM];
__device__ __align__(16) bf16  g_A1  [MENC * Z_DIM];     // [dz(4096); z_c(128)]
__device__ __align__(16) bf16  g_U1  [MENC * H_DIM];
__device__ __align__(16) bf16  g_V1  [MENC * H_DIM];     // [t1(4096); h1(128)]
__device__ __align__(16) bf16  g_U2  [MENC * H_DIM];
__device__ __align__(16) bf16  g_S2  [RTOT * H_DIM];     // t2 + h2 (recon folded)
__device__ float g_w[RTOT];
__device__ float g_loss;

__device__ __forceinline__ unsigned smem_u32(const void* p) {
    return (unsigned)__cvta_generic_to_shared(p);
}
__device__ __forceinline__ void cpasync16(unsigned dst, const void* src) {
    asm volatile("cp.async.cg.shared.global [%0], [%1], 16;" :: "r"(dst), "l"(src));
}
__device__ __forceinline__ void unpack8(uint4 u, float* f) {
    const __nv_bfloat162* p = (const __nv_bfloat162*)&u;
#pragma unroll
    for (int i = 0; i < 4; i++) {
        float2 t = __bfloat1622float2(p[i]);
        f[2 * i] = t.x; f[2 * i + 1] = t.y;
    }
}
__device__ __forceinline__ uint4 pack8(const float* f) {
    uint4 u;
    __nv_bfloat162* p = (__nv_bfloat162*)&u;
#pragma unroll
    for (int i = 0; i < 4; i++) p[i] = __floats2bfloat162_rn(f[2 * i], f[2 * i + 1]);
    return u;
}

// ---------------------------------------------------------------------------
// bf16 tensor-core GEMM: C(M,N) = epi(A(M,K) @ B(K,N)), fp32 accumulate.
// Block tile 128x128, K-chunk 32, 3-stage cp.async, warp tile 64x32, 2 CTA/SM.
// ---------------------------------------------------------------------------
template<int EPI>
__global__ __launch_bounds__(256, 2)
void mma_gemm(const bf16* __restrict__ A, const bf16* __restrict__ B,
              bf16* __restrict__ Cout, int M, int N, int K,
              const float* __restrict__ bias,
              const float* __restrict__ xnn,        // [M, N] for EPI_LOSS
              const float* __restrict__ wts,        // [M]   for EPI_LOSS
              float* __restrict__ lossAcc)
{
    extern __shared__ __align__(16) char dsm[];
    __shared__ float red[256];

    const int tid  = threadIdx.x;
    const int lane = tid & 31;
    const int wid  = tid >> 5;
    const int bm = blockIdx.y * 128;
    const int bn = blockIdx.x * 128;
    const int warpM = (wid >> 2) * 64;
    const int warpN = (wid & 3) * 32;

    const int ar = tid >> 2;
    const int ac = (tid & 3) * 8;
    const int br = tid >> 3;
    const int bc = (tid & 7) * 8;

    const bf16* Ag  = A + (size_t)(bm + ar) * K + ac;
    const bf16* Ag2 = Ag + (size_t)64 * K;
    const bf16* Bg  = B + (size_t)br * N + bn + bc;

    const unsigned dyn0 = smem_u32(dsm);
    const unsigned oA0 = (unsigned)((ar * SA + ac) * 2);
    const unsigned oA1 = (unsigned)(((ar + 64) * SA + ac) * 2);
    const unsigned oB0 = (unsigned)(ASZ + (br * SB + bc) * 2);
    const unsigned oB1 = (unsigned)(ASZ + (br * SB + bc + 64) * 2);

    float acc[4][4][4];
#pragma unroll
    for (int i = 0; i < 4; i++)
#pragma unroll
        for (int j = 0; j < 4; j++)
#pragma unroll
            for (int q = 0; q < 4; q++) acc[i][j][q] = 0.f;

    const int KT = K / 32;

    auto load_tile = [&](int kt) {
        if (kt < KT) {
            const unsigned base = dyn0 + (kt % NSTAGE) * STG;
            const bf16* ga  = Ag  + (size_t)kt * 32;
            const bf16* ga2 = Ag2 + (size_t)kt * 32;
            const bf16* gb  = Bg  + (size_t)kt * 32 * N;
            cpasync16(base + oA0, ga);
            cpasync16(base + oA1, ga2);
            cpasync16(base + oB0, gb);
            cpasync16(base + oB1, gb + 64);
        }
        asm volatile("cp.async.commit_group;" ::: "memory");
    };

    load_tile(0);
    load_tile(1);

    for (int kt = 0; kt < KT; kt++) {
        asm volatile("cp.async.wait_group 1;" ::: "memory");
        __syncthreads();
        load_tile(kt + 2);

        const unsigned base = dyn0 + (kt % NSTAGE) * STG;
        const unsigned abase = base;
        const unsigned bbase = base + ASZ;
#pragma unroll
        for (int ks = 0; ks < 32; ks += 16) {
            unsigned a[4][4];
#pragma unroll
            for (int ms = 0; ms < 4; ms++) {
                unsigned addr = abase +
                    ((warpM + ms * 16 + (lane & 15)) * SA + ks + (lane >> 4) * 8) * 2;
                asm volatile("ldmatrix.sync.aligned.m8n8.x4.shared.b16 {%0,%1,%2,%3}, [%4];"
                             : "=r"(a[ms][0]), "=r"(a[ms][1]), "=r"(a[ms][2]), "=r"(a[ms][3])
                             : "r"(addr));
            }
            unsigned b[4][2];
#pragma unroll
            for (int np = 0; np < 2; np++) {
                unsigned addr = bbase +
                    ((ks + (lane & 15)) * SB + warpN + np * 16 + (lane >> 4) * 8) * 2;
                unsigned r0, r1, r2, r3;
                asm volatile("ldmatrix.sync.aligned.m8n8.x4.trans.shared.b16 {%0,%1,%2,%3}, [%4];"
                             : "=r"(r0), "=r"(r1), "=r"(r2), "=r"(r3) : "r"(addr));
                b[np * 2][0] = r0; b[np * 2][1] = r1;
                b[np * 2 + 1][0] = r2; b[np * 2 + 1][1] = r3;
            }
#pragma unroll
            for (int ms = 0; ms < 4; ms++)
#pragma unroll
                for (int ns = 0; ns < 4; ns++)
                    asm volatile(
                        "mma.sync.aligned.m16n8k16.row.col.f32.bf16.bf16.f32 "
                        "{%0,%1,%2,%3}, {%4,%5,%6,%7}, {%8,%9}, {%0,%1,%2,%3};"
                        : "+f"(acc[ms][ns][0]), "+f"(acc[ms][ns][1]),
                          "+f"(acc[ms][ns][2]), "+f"(acc[ms][ns][3])
                        : "r"(a[ms][0]), "r"(a[ms][1]), "r"(a[ms][2]), "r"(a[ms][3]),
                          "r"(b[ns][0]), "r"(b[ns][1]));
        }
        __syncthreads();
    }

    // ------------------------------ epilogue ------------------------------
    if (EPI == EPI_LOSS) {
        // diff = xnn - (acc + bias);  lsum += w * diff^2   (recon folded into A)
        float lsum = 0.f;
#pragma unroll
        for (int ms = 0; ms < 4; ms++) {
            const int r0 = bm + warpM + ms * 16 + (lane >> 2);
            const int r1 = r0 + 8;
            const float w0 = wts[r0], w1 = wts[r1];
#pragma unroll
            for (int ns = 0; ns < 4; ns++) {
                const int c = bn + warpN + ns * 8 + (lane & 3) * 2;
                float2 x0 = *(const float2*)(xnn + (size_t)r0 * N + c);
                float2 x1 = *(const float2*)(xnn + (size_t)r1 * N + c);
                const float b_0 = bias[c], b_1 = bias[c + 1];
                float d0 = x0.x - (acc[ms][ns][0] + b_0);
                float d1 = x0.y - (acc[ms][ns][1] + b_1);
                float d2 = x1.x - (acc[ms][ns][2] + b_0);
                float d3 = x1.y - (acc[ms][ns][3] + b_1);
                lsum += w0 * (d0 * d0 + d1 * d1) + w1 * (d2 * d2 + d3 * d3);
            }
        }
        red[tid] = lsum;
        __syncthreads();
        for (int s2 = 128; s2 > 0; s2 >>= 1) {
            if (tid < s2) red[tid] += red[tid + s2];
            __syncthreads();
        }
        if (tid == 0) atomicAdd(lossAcc, red[0]);
    } else {
#pragma unroll
        for (int ms = 0; ms < 4; ms++) {
            const int r0 = bm + warpM + ms * 16 + (lane >> 2);
            const int r1 = r0 + 8;
#pragma unroll
            for (int ns = 0; ns < 4; ns++) {
                const int c = bn + warpN + ns * 8 + (lane & 3) * 2;
                float v0 = acc[ms][ns][0], v1 = acc[ms][ns][1];
                float v2 = acc[ms][ns][2], v3 = acc[ms][ns][3];
                if (EPI == EPI_BIAS_RELU_BF) {
                    const float b_0 = bias[c], b_1 = bias[c + 1];
                    v0 = fmaxf(v0 + b_0, 0.f); v1 = fmaxf(v1 + b_1, 0.f);
                    v2 = fmaxf(v2 + b_0, 0.f); v3 = fmaxf(v3 + b_1, 0.f);
                }
                *(__nv_bfloat162*)(Cout + (size_t)r0 * N + c) = __floats2bfloat162_rn(v0, v1);
                *(__nv_bfloat162*)(Cout + (size_t)r1 * N + c) = __floats2bfloat162_rn(v2, v3);
            }
        }
    }
}

// ---------------------------------------------------------------------------
// small GEMM, N=32 latent projection: C(M,32) = A(M,K)@B(K,32) + bias, fp32 out
// ---------------------------------------------------------------------------
__global__ void gemm_n32_bf(const bf16* __restrict__ A, const bf16* __restrict__ B,
                            const float* __restrict__ bias, float* __restrict__ C,
                            int K)
{
    const int col = threadIdx.x & 31;
    const int row = blockIdx.x * 8 + (threadIdx.x >> 5);
    const bf16* a = A + (size_t)row * K;
    float s = bias[col];
    for (int k = 0; k < K; k += 8) {
        uint4 raw = *(const uint4*)(a + k);
        const __nv_bfloat162* av = (const __nv_bfloat162*)&raw;
#pragma unroll
        for (int i = 0; i < 4; i++) {
            float2 f = __bfloat1622float2(av[i]);
            s = fmaf(f.x, __bfloat162float(B[(k + 2 * i) * 32 + col]), s);
            s = fmaf(f.y, __bfloat162float(B[(k + 2 * i + 1) * 32 + col]), s);
        }
    }
    C[(size_t)row * 32 + col] = s;
}

// ---------------------------------------------------------------------------
// fused x conversion + binary-kernel weights (one block per row)
// ---------------------------------------------------------------------------
__global__ void xconv_k(const float* __restrict__ xnn, const float* __restrict__ xc,
                        bf16* __restrict__ Abf, float* __restrict__ w)
{
    const int r = blockIdx.x;
    const int t = threadIdx.x;
    bf16* orow = Abf + (size_t)r * D_DIM;
    if (r < RTOT) {
        const float* xr = xnn + (size_t)r * D_DIM;
        const float* xb = xc + (size_t)(r >> 5) * D_DIM;
        float s = 0.f;
#pragma unroll
        for (int i = 0; i < 3; i++) {
            const int idx = (t + i * 256) * 4;
            float4 v = *(const float4*)(xr + idx);
            float4 c = *(const float4*)(xb + idx);
            *(__nv_bfloat162*)(orow + idx)     = __floats2bfloat162_rn(v.x, v.y);
            *(__nv_bfloat162*)(orow + idx + 2) = __floats2bfloat162_rn(v.z, v.w);
            float d0 = v.x - c.x, d1 = v.y - c.y, d2 = v.z - c.z, d3 = v.w - c.w;
            s += d0 * d0 + d1 * d1 + d2 * d2 + d3 * d3;
        }
        __shared__ float red[256];
        red[t] = s;
        __syncthreads();
        for (int k = 128; k > 0; k >>= 1) {
            if (t < k) red[t] += red[t + k];
            __syncthreads();
        }
        if (t == 0) w[r] = (sqrtf(red[0]) > 1e-12f) ? 1.0f : 0.5f;
    } else {
        const float* xr = xc + (size_t)(r - RTOT) * D_DIM;
#pragma unroll
        for (int i = 0; i < 3; i++) {
            const int idx = (t + i * 256) * 4;
            float4 v = *(const float4*)(xr + idx);
            *(__nv_bfloat162*)(orow + idx)     = __floats2bfloat162_rn(v.x, v.y);
            *(__nv_bfloat162*)(orow + idx + 2) = __floats2bfloat162_rn(v.z, v.w);
        }
    }
}

// ---------------------------------------------------------------------------
// batched conversion of all 6 weight matrices
// ---------------------------------------------------------------------------
#define W1SZ (D_DIM * H_DIM)
#define W2SZ (H_DIM * H_DIM)
#define W3SZ (H_DIM * Z_DIM)
#define WTOT (2 * W1SZ + 2 * W2SZ + 2 * W3SZ)

__global__ void wconv_k(const float* __restrict__ We1, const float* __restrict__ We2,
                        const float* __restrict__ We3, const float* __restrict__ Wd1,
                        const float* __restrict__ Wd2, const float* __restrict__ Wd3,
                        bf16* __restrict__ oWe1, bf16* __restrict__ oWe2,
                        bf16* __restrict__ oWe3, bf16* __restrict__ oWd1,
                        bf16* __restrict__ oWd2, bf16* __restrict__ oWd3)
{
    long long i = (long long)(blockIdx.x * 256 + threadIdx.x) * 8;
    if (i >= WTOT) return;
    const float* in; bf16* out; long long off;
    if      (i < W1SZ)                       { in = We1; out = oWe1; off = 0; }
    else if (i < W1SZ + W2SZ)                { in = We2; out = oWe2; off = W1SZ; }
    else if (i < W1SZ + W2SZ + W3SZ)         { in = We3; out = oWe3; off = W1SZ + W2SZ; }
    else if (i < W1SZ + W2SZ + 2 * W3SZ)     { in = Wd1; out = oWd1; off = W1SZ + W2SZ + W3SZ; }
    else if (i < W1SZ + 2 * W2SZ + 2 * W3SZ) { in = Wd2; out = oWd2; off = W1SZ + W2SZ + 2 * W3SZ; }
    else                                     { in = Wd3; out = oWd3; off = W1SZ + 2 * W2SZ + 2 * W3SZ; }
    const long long k = i - off;
    float4 v0 = *(const float4*)(in + k);
    float4 v1 = *(const float4*)(in + k + 4);
    *(__nv_bfloat162*)(out + k)     = __floats2bfloat162_rn(v0.x, v0.y);
    *(__nv_bfloat162*)(out + k + 2) = __floats2bfloat162_rn(v0.z, v0.w);
    *(__nv_bfloat162*)(out + k + 4) = __floats2bfloat162_rn(v1.x, v1.y);
    *(__nv_bfloat162*)(out + k + 6) = __floats2bfloat162_rn(v1.z, v1.w);
}

// A1 = [dz(4096); z_c(128)] bf16 (K=32 rows), and zero the loss accumulator
__global__ void dz_k(const float* __restrict__ Z, bf16* __restrict__ A1,
                     float* __restrict__ loss)
{
    const int idx = blockIdx.x * 256 + threadIdx.x;   // < MENC*32
    if (idx == 0) *loss = 0.f;
    const int r = idx >> 5, j = idx & 31;
    float v;
    if (r < RTOT) v = Z[idx] - Z[(RTOT + (r >> 5)) * Z_DIM + j];
    else          v = Z[idx];
    A1[idx] = __float2bfloat16(v);
}

// E1: V1[r<4096] = t1 = 1[u_c+b>0] * u_nn ;  V1[4096+rc] = h1 = relu(u_c+b)
__global__ void eps1_k(const bf16* __restrict__ U1, const float* __restrict__ bd1,
                       bf16* __restrict__ V1)
{
    const long long i = (long long)(blockIdx.x * 256 + threadIdx.x) * 8;
    float un[8], uc[8], bv[8], o[8];
    if (i < (long long)RTOT * H_DIM) {
        const int r = (int)(i >> 10), j = (int)(i & 1023), b = r >> 5;
        unpack8(*(const uint4*)(U1 + (size_t)r * H_DIM + j), un);
        unpack8(*(const uint4*)(U1 + (size_t)(RTOT + b) * H_DIM + j), uc);
        *(float4*)bv = *(const float4*)(bd1 + j);
        *(float4*)(bv + 4) = *(const float4*)(bd1 + j + 4);
#pragma unroll
        for (int k = 0; k < 8; k++) o[k] = (uc[k] + bv[k] > 0.f) ? un[k] : 0.f;
        *(uint4*)(V1 + (size_t)r * H_DIM + j) = pack8(o);
    } else {
        const long long k2 = i - (long long)RTOT * H_DIM;
        const int rc = (int)(k2 >> 10), j = (int)(k2 & 1023);
        unpack8(*(const uint4*)(U1 + (size_t)(RTOT + rc) * H_DIM + j), uc);
        *(float4*)bv = *(const float4*)(bd1 + j);
        *(float4*)(bv + 4) = *(const float4*)(bd1 + j + 4);
#pragma unroll
        for (int k = 0; k < 8; k++) o[k] = fmaxf(uc[k] + bv[k], 0.f);
        *(uint4*)(V1 + (size_t)(RTOT + rc) * H_DIM + j) = pack8(o);
    }
}

// E2: S2[r] = u_c'>0 ? (u_c' + u_nn) : 0   where u_c' = U2_center + bd2
// (= h2 + t2: recon folded into the loss GEMM's A operand)
__global__ void eps2_k(const bf16* __restrict__ U2, const float* __restrict__ bd2,
                       bf16* __restrict__ S2)
{
    const long long i = (long long)(blockIdx.x * 256 + threadIdx.x) * 8;
    const int r = (int)(i >> 10), j = (int)(i & 1023), b = r >> 5;
    float un[8], uc[8], bv[8], o[8];
    unpack8(*(const uint4*)(U2 + (size_t)r * H_DIM + j), un);
    unpack8(*(const uint4*)(U2 + (size_t)(RTOT + b) * H_DIM + j), uc);
    *(float4*)bv = *(const float4*)(bd2 + j);
    *(float4*)(bv + 4) = *(const float4*)(bd2 + j + 4);
#pragma unroll
    for (int k = 0; k < 8; k++) {
        const float u = uc[k] + bv[k];
        o[k] = (u > 0.f) ? (u + un[k]) : 0.f;
    }
    *(uint4*)(S2 + (size_t)r * H_DIM + j) = pack8(o);
}

__global__ void final_k(const float* loss, float* out) { out[0] = *loss * (1.0f / (float)RTOT); }

// ---------------------------------------------------------------------------

extern "C" void kernel_launch(void* const* d_in, const int* in_sizes, int n_in,
                              void* d_out, int out_size)
{
    (void)in_sizes; (void)n_in; (void)out_size;
    const float* x_c  = (const float*)d_in[0];
    const float* x_nn = (const float*)d_in[1];
    const float* We1  = (const float*)d_in[2];
    const float* be1  = (const float*)d_in[3];
    const float* We2  = (const float*)d_in[4];
    const float* be2  = (const float*)d_in[5];
    const float* We3  = (const float*)d_in[6];
    const float* be3  = (const float*)d_in[7];
    const float* Wd1  = (const float*)d_in[8];
    const float* bd1  = (const float*)d_in[9];
    const float* Wd2  = (const float*)d_in[10];
    const float* bd2  = (const float*)d_in[11];
    const float* Wd3  = (const float*)d_in[12];
    const float* bd3  = (const float*)d_in[13];
    float* out = (float*)d_out;

    bf16 *Abf, *We1b, *We2b, *We3b, *Wd1b, *Wd2b, *Wd3b;
    bf16 *H1b, *H2b, *A1, *U1, *V1, *U2, *S2;
    float *Z, *w, *loss;
    cudaGetSymbolAddress((void**)&Abf,  g_Abf);
    cudaGetSymbolAddress((void**)&We1b, g_We1b);
    cudaGetSymbolAddress((void**)&We2b, g_We2b);
    cudaGetSymbolAddress((void**)&We3b, g_We3b);
    cudaGetSymbolAddress((void**)&Wd1b, g_Wd1b);
    cudaGetSymbolAddress((void**)&Wd2b, g_Wd2b);
    cudaGetSymbolAddress((void**)&Wd3b, g_Wd3b);
    cudaGetSymbolAddress((void**)&H1b,  g_H1b);
    cudaGetSymbolAddress((void**)&H2b,  g_H2b);
    cudaGetSymbolAddress((void**)&Z,    g_Z);
    cudaGetSymbolAddress((void**)&A1,   g_A1);
    cudaGetSymbolAddress((void**)&U1,   g_U1);
    cudaGetSymbolAddress((void**)&V1,   g_V1);
    cudaGetSymbolAddress((void**)&U2,   g_U2);
    cudaGetSymbolAddress((void**)&S2,   g_S2);
    cudaGetSymbolAddress((void**)&w,    g_w);
    cudaGetSymbolAddress((void**)&loss, g_loss);

    cudaFuncSetAttribute(mma_gemm<EPI_BIAS_RELU_BF>, cudaFuncAttributeMaxDynamicSharedMemorySize, SMEM_DYN);
    cudaFuncSetAttribute(mma_gemm<EPI_NONE_BF>,      cudaFuncAttributeMaxDynamicSharedMemorySize, SMEM_DYN);
    cudaFuncSetAttribute(mma_gemm<EPI_LOSS>,         cudaFuncAttributeMaxDynamicSharedMemorySize, SMEM_DYN);

    const dim3 blk(256);
    auto ggrid = [](int M, int N) { return dim3(N / 128, M / 128); };

    // prologue conversions
    xconv_k<<<MENC, blk>>>(x_nn, x_c, Abf, w);
    wconv_k<<<(WTOT / 8 + 255) / 256, blk>>>(We1, We2, We3, Wd1, Wd2, Wd3,
                                             We1b, We2b, We3b, Wd1b, Wd2b, Wd3b);

    // encoder (x_nn ++ x_c merged, M = 4224)
    mma_gemm<EPI_BIAS_RELU_BF><<<ggrid(MENC, H_DIM), blk, SMEM_DYN>>>(
        Abf, We1b, H1b, MENC, H_DIM, D_DIM, be1, nullptr, nullptr, nullptr);
    mma_gemm<EPI_BIAS_RELU_BF><<<ggrid(MENC, H_DIM), blk, SMEM_DYN>>>(
        H1b, We2b, H2b, MENC, H_DIM, H_DIM, be2, nullptr, nullptr, nullptr);
    gemm_n32_bf<<<MENC / 8, blk>>>(H2b, We3b, be3, Z, H_DIM);

    // A1 = [dz; z_c] (+ loss zero)
    dz_k<<<(MENC * Z_DIM) / 256, blk>>>(Z, A1, loss);

    // merged decoder+JVP chain (center rows ride along; hess == 0 for ReLU MLP)
    mma_gemm<EPI_NONE_BF><<<ggrid(MENC, H_DIM), blk, SMEM_DYN>>>(
        A1, Wd1b, U1, MENC, H_DIM, Z_DIM, nullptr, nullptr, nullptr, nullptr);
    eps1_k<<<(MENC * H_DIM) / (256 * 8), blk>>>(U1, bd1, V1);
    mma_gemm<EPI_NONE_BF><<<ggrid(MENC, H_DIM), blk, SMEM_DYN>>>(
        V1, Wd2b, U2, MENC, H_DIM, H_DIM, nullptr, nullptr, nullptr, nullptr);
    eps2_k<<<(RTOT * H_DIM) / (256 * 8), blk>>>(U2, bd2, S2);

    // loss GEMM: diff = x_nn - (S2 @ Wd3 + bd3); recon folded into S2
    mma_gemm<EPI_LOSS><<<ggrid(RTOT, D_DIM), blk, SMEM_DYN>>>(
        S2, Wd3b, nullptr, RTOT, D_DIM, H_DIM, bd3, x_nn, w, loss);

    final_k<<<1, 1>>>(loss, out);
}

// round 13
// speedup vs baseline: 1.5204x; 1.5204x over previous
#include <cuda_runtime.h>
#include <cuda_bf16.h>
#include <cstdint>
#include <math.h>

typedef __nv_bfloat16 bf16;

#define D_DIM 3072
#define H_DIM 1024
#define Z_DIM 32
#define BS    128
#define NN    32
#define RTOT  4096
#define MENC  4224

// GEMM tile: 128 x 128, K-chunk 32, 8 warps (2x4), warp tile 64x32 (proven)
#define SA 40
#define SB 136
#define ASZ (128 * SA * 2)
#define BSZ (32 * SB * 2)
#define STG (ASZ + BSZ)
#define NSTAGE 3
#define SMEM_DYN (NSTAGE * STG)

enum { EPI_BIAS_RELU_BF = 0, EPI_NONE_BF = 1, EPI_LOSS = 2 };

// ------------------------- scratch (no allocation) -------------------------
__device__ __align__(16) bf16  g_Abf [MENC * D_DIM];
__device__ __align__(16) bf16  g_We1b[D_DIM * H_DIM];
__device__ __align__(16) bf16  g_We2b[H_DIM * H_DIM];
__device__ __align__(16) bf16  g_We3b[H_DIM * Z_DIM];
__device__ __align__(16) bf16  g_Wd1b[Z_DIM * H_DIM];
__device__ __align__(16) bf16  g_Wd2b[H_DIM * H_DIM];
__device__ __align__(16) bf16  g_Wd3b[H_DIM * D_DIM];
__device__ __align__(16) bf16  g_H1b [MENC * H_DIM];
__device__ __align__(16) bf16  g_H2b [MENC * H_DIM];
__device__ __align__(16) float g_Z   [MENC * Z_DIM];
__device__ __align__(16) bf16  g_A1  [MENC * Z_DIM];     // [dz(4096); z_c(128)]
__device__ __align__(16) bf16  g_U1  [MENC * H_DIM];
__device__ __align__(16) bf16  g_V1  [MENC * H_DIM];     // [t1(4096); h1(128)]
__device__ __align__(16) bf16  g_U2  [MENC * H_DIM];
__device__ __align__(16) bf16  g_S2  [RTOT * H_DIM];     // t2 + h2 (recon folded)
__device__ float g_w[RTOT];
__device__ float g_loss;

__device__ __forceinline__ unsigned smem_u32(const void* p) {
    return (unsigned)__cvta_generic_to_shared(p);
}
__device__ __forceinline__ void cpasync16(unsigned dst, const void* src) {
    asm volatile("cp.async.cg.shared.global [%0], [%1], 16;" :: "r"(dst), "l"(src));
}
__device__ __forceinline__ void unpack8(uint4 u, float* f) {
    const __nv_bfloat162* p = (const __nv_bfloat162*)&u;
#pragma unroll
    for (int i = 0; i < 4; i++) {
        float2 t = __bfloat1622float2(p[i]);
        f[2 * i] = t.x; f[2 * i + 1] = t.y;
    }
}
__device__ __forceinline__ uint4 pack8(const float* f) {
    uint4 u;
    __nv_bfloat162* p = (__nv_bfloat162*)&u;
#pragma unroll
    for (int i = 0; i < 4; i++) p[i] = __floats2bfloat162_rn(f[2 * i], f[2 * i + 1]);
    return u;
}

// ---------------------------------------------------------------------------
// bf16 tensor-core GEMM: C(M,N) = epi(A(M,K) @ B(K,N)), fp32 accumulate.
// Block tile 128x128, K-chunk 32, 3-stage cp.async, warp tile 64x32, 2 CTA/SM.
// ---------------------------------------------------------------------------
template<int EPI>
__global__ __launch_bounds__(256, 2)
void mma_gemm(const bf16* __restrict__ A, const bf16* __restrict__ B,
              bf16* __restrict__ Cout, int M, int N, int K,
              const float* __restrict__ bias,
              const float* __restrict__ xnn,        // [M, N] for EPI_LOSS
              const float* __restrict__ wts,        // [M]   for EPI_LOSS
              float* __restrict__ lossAcc)
{
    extern __shared__ __align__(16) char dsm[];
    __shared__ float red[256];

    const int tid  = threadIdx.x;
    const int lane = tid & 31;
    const int wid  = tid >> 5;
    const int bm = blockIdx.y * 128;
    const int bn = blockIdx.x * 128;
    const int warpM = (wid >> 2) * 64;
    const int warpN = (wid & 3) * 32;

    const int ar = tid >> 2;
    const int ac = (tid & 3) * 8;
    const int br = tid >> 3;
    const int bc = (tid & 7) * 8;

    const bf16* Ag  = A + (size_t)(bm + ar) * K + ac;
    const bf16* Ag2 = Ag + (size_t)64 * K;
    const bf16* Bg  = B + (size_t)br * N + bn + bc;

    const unsigned dyn0 = smem_u32(dsm);
    const unsigned oA0 = (unsigned)((ar * SA + ac) * 2);
    const unsigned oA1 = (unsigned)(((ar + 64) * SA + ac) * 2);
    const unsigned oB0 = (unsigned)(ASZ + (br * SB + bc) * 2);
    const unsigned oB1 = (unsigned)(ASZ + (br * SB + bc + 64) * 2);

    float acc[4][4][4];
#pragma unroll
    for (int i = 0; i < 4; i++)
#pragma unroll
        for (int j = 0; j < 4; j++)
#pragma unroll
            for (int q = 0; q < 4; q++) acc[i][j][q] = 0.f;

    const int KT = K / 32;

    auto load_tile = [&](int kt) {
        if (kt < KT) {
            const unsigned base = dyn0 + (kt % NSTAGE) * STG;
            const bf16* ga  = Ag  + (size_t)kt * 32;
            const bf16* ga2 = Ag2 + (size_t)kt * 32;
            const bf16* gb  = Bg  + (size_t)kt * 32 * N;
            cpasync16(base + oA0, ga);
            cpasync16(base + oA1, ga2);
            cpasync16(base + oB0, gb);
            cpasync16(base + oB1, gb + 64);
        }
        asm volatile("cp.async.commit_group;" ::: "memory");
    };

    load_tile(0);
    load_tile(1);

    for (int kt = 0; kt < KT; kt++) {
        asm volatile("cp.async.wait_group 1;" ::: "memory");
        __syncthreads();
        load_tile(kt + 2);

        const unsigned base = dyn0 + (kt % NSTAGE) * STG;
        const unsigned abase = base;
        const unsigned bbase = base + ASZ;
#pragma unroll
        for (int ks = 0; ks < 32; ks += 16) {
            unsigned a[4][4];
#pragma unroll
            for (int ms = 0; ms < 4; ms++) {
                unsigned addr = abase +
                    ((warpM + ms * 16 + (lane & 15)) * SA + ks + (lane >> 4) * 8) * 2;
                asm volatile("ldmatrix.sync.aligned.m8n8.x4.shared.b16 {%0,%1,%2,%3}, [%4];"
                             : "=r"(a[ms][0]), "=r"(a[ms][1]), "=r"(a[ms][2]), "=r"(a[ms][3])
                             : "r"(addr));
            }
            unsigned b[4][2];
#pragma unroll
            for (int np = 0; np < 2; np++) {
                unsigned addr = bbase +
                    ((ks + (lane & 15)) * SB + warpN + np * 16 + (lane >> 4) * 8) * 2;
                unsigned r0, r1, r2, r3;
                asm volatile("ldmatrix.sync.aligned.m8n8.x4.trans.shared.b16 {%0,%1,%2,%3}, [%4];"
                             : "=r"(r0), "=r"(r1), "=r"(r2), "=r"(r3) : "r"(addr));
                b[np * 2][0] = r0; b[np * 2][1] = r1;
                b[np * 2 + 1][0] = r2; b[np * 2 + 1][1] = r3;
            }
#pragma unroll
            for (int ms = 0; ms < 4; ms++)
#pragma unroll
                for (int ns = 0; ns < 4; ns++)
                    asm volatile(
                        "mma.sync.aligned.m16n8k16.row.col.f32.bf16.bf16.f32 "
                        "{%0,%1,%2,%3}, {%4,%5,%6,%7}, {%8,%9}, {%0,%1,%2,%3};"
                        : "+f"(acc[ms][ns][0]), "+f"(acc[ms][ns][1]),
                          "+f"(acc[ms][ns][2]), "+f"(acc[ms][ns][3])
                        : "r"(a[ms][0]), "r"(a[ms][1]), "r"(a[ms][2]), "r"(a[ms][3]),
                          "r"(b[ns][0]), "r"(b[ns][1]));
        }
        __syncthreads();
    }

    // ------------------------------ epilogue ------------------------------
    if (EPI == EPI_LOSS) {
        // diff = xnn - (acc + bias);  lsum += w * diff^2   (recon folded into A)
        float lsum = 0.f;
#pragma unroll
        for (int ms = 0; ms < 4; ms++) {
            const int r0 = bm + warpM + ms * 16 + (lane >> 2);
            const int r1 = r0 + 8;
            const float w0 = wts[r0], w1 = wts[r1];
#pragma unroll
            for (int ns = 0; ns < 4; ns++) {
                const int c = bn + warpN + ns * 8 + (lane & 3) * 2;
                float2 x0 = *(const float2*)(xnn + (size_t)r0 * N + c);
                float2 x1 = *(const float2*)(xnn + (size_t)r1 * N + c);
                const float b_0 = bias[c], b_1 = bias[c + 1];
                float d0 = x0.x - (acc[ms][ns][0] + b_0);
                float d1 = x0.y - (acc[ms][ns][1] + b_1);
                float d2 = x1.x - (acc[ms][ns][2] + b_0);
                float d3 = x1.y - (acc[ms][ns][3] + b_1);
                lsum += w0 * (d0 * d0 + d1 * d1) + w1 * (d2 * d2 + d3 * d3);
            }
        }
        red[tid] = lsum;
        __syncthreads();
        for (int s2 = 128; s2 > 0; s2 >>= 1) {
            if (tid < s2) red[tid] += red[tid + s2];
            __syncthreads();
        }
        if (tid == 0) atomicAdd(lossAcc, red[0]);
    } else {
#pragma unroll
        for (int ms = 0; ms < 4; ms++) {
            const int r0 = bm + warpM + ms * 16 + (lane >> 2);
            const int r1 = r0 + 8;
#pragma unroll
            for (int ns = 0; ns < 4; ns++) {
                const int c = bn + warpN + ns * 8 + (lane & 3) * 2;
                float v0 = acc[ms][ns][0], v1 = acc[ms][ns][1];
                float v2 = acc[ms][ns][2], v3 = acc[ms][ns][3];
                if (EPI == EPI_BIAS_RELU_BF) {
                    const float b_0 = bias[c], b_1 = bias[c + 1];
                    v0 = fmaxf(v0 + b_0, 0.f); v1 = fmaxf(v1 + b_1, 0.f);
                    v2 = fmaxf(v2 + b_0, 0.f); v3 = fmaxf(v3 + b_1, 0.f);
                }
                *(__nv_bfloat162*)(Cout + (size_t)r0 * N + c) = __floats2bfloat162_rn(v0, v1);
                *(__nv_bfloat162*)(Cout + (size_t)r1 * N + c) = __floats2bfloat162_rn(v2, v3);
            }
        }
    }
}

// ---------------------------------------------------------------------------
// small GEMM, N=32 latent projection: C(M,32) = A(M,K)@B(K,32) + bias, fp32 out
// ---------------------------------------------------------------------------
__global__ void gemm_n32_bf(const bf16* __restrict__ A, const bf16* __restrict__ B,
                            const float* __restrict__ bias, float* __restrict__ C,
                            int K)
{
    const int col = threadIdx.x & 31;
    const int row = blockIdx.x * 8 + (threadIdx.x >> 5);
    const bf16* a = A + (size_t)row * K;
    float s = bias[col];
    for (int k = 0; k < K; k += 8) {
        uint4 raw = *(const uint4*)(a + k);
        const __nv_bfloat162* av = (const __nv_bfloat162*)&raw;
#pragma unroll
        for (int i = 0; i < 4; i++) {
            float2 f = __bfloat1622float2(av[i]);
            s = fmaf(f.x, __bfloat162float(B[(k + 2 * i) * 32 + col]), s);
            s = fmaf(f.y, __bfloat162float(B[(k + 2 * i + 1) * 32 + col]), s);
        }
    }
    C[(size_t)row * 32 + col] = s;
}

// ---------------------------------------------------------------------------
// fused x conversion + binary-kernel weights (one block per row)
// ---------------------------------------------------------------------------
__global__ void xconv_k(const float* __restrict__ xnn, const float* __restrict__ xc,
                        bf16* __restrict__ Abf, float* __restrict__ w)
{
    const int r = blockIdx.x;
    const int t = threadIdx.x;
    bf16* orow = Abf + (size_t)r * D_DIM;
    if (r < RTOT) {
        const float* xr = xnn + (size_t)r * D_DIM;
        const float* xb = xc + (size_t)(r >> 5) * D_DIM;
        float s = 0.f;
#pragma unroll
        for (int i = 0; i < 3; i++) {
            const int idx = (t + i * 256) * 4;
            float4 v = *(const float4*)(xr + idx);
            float4 c = *(const float4*)(xb + idx);
            *(__nv_bfloat162*)(orow + idx)     = __floats2bfloat162_rn(v.x, v.y);
            *(__nv_bfloat162*)(orow + idx + 2) = __floats2bfloat162_rn(v.z, v.w);
            float d0 = v.x - c.x, d1 = v.y - c.y, d2 = v.z - c.z, d3 = v.w - c.w;
            s += d0 * d0 + d1 * d1 + d2 * d2 + d3 * d3;
        }
        __shared__ float red[256];
        red[t] = s;
        __syncthreads();
        for (int k = 128; k > 0; k >>= 1) {
            if (t < k) red[t] += red[t + k];
            __syncthreads();
        }
        if (t == 0) w[r] = (sqrtf(red[0]) > 1e-12f) ? 1.0f : 0.5f;
    } else {
        const float* xr = xc + (size_t)(r - RTOT) * D_DIM;
#pragma unroll
        for (int i = 0; i < 3; i++) {
            const int idx = (t + i * 256) * 4;
            float4 v = *(const float4*)(xr + idx);
            *(__nv_bfloat162*)(orow + idx)     = __floats2bfloat162_rn(v.x, v.y);
            *(__nv_bfloat162*)(orow + idx + 2) = __floats2bfloat162_rn(v.z, v.w);
        }
    }
}

// ---------------------------------------------------------------------------
// batched conversion of all 6 weight matrices
// ---------------------------------------------------------------------------
#define W1SZ (D_DIM * H_DIM)
#define W2SZ (H_DIM * H_DIM)
#define W3SZ (H_DIM * Z_DIM)
#define WTOT (2 * W1SZ + 2 * W2SZ + 2 * W3SZ)

__global__ void wconv_k(const float* __restrict__ We1, const float* __restrict__ We2,
                        const float* __restrict__ We3, const float* __restrict__ Wd1,
                        const float* __restrict__ Wd2, const float* __restrict__ Wd3,
                        bf16* __restrict__ oWe1, bf16* __restrict__ oWe2,
                        bf16* __restrict__ oWe3, bf16* __restrict__ oWd1,
                        bf16* __restrict__ oWd2, bf16* __restrict__ oWd3)
{
    long long i = (long long)(blockIdx.x * 256 + threadIdx.x) * 8;
    if (i >= WTOT) return;
    const float* in; bf16* out; long long off;
    if      (i < W1SZ)                       { in = We1; out = oWe1; off = 0; }
    else if (i < W1SZ + W2SZ)                { in = We2; out = oWe2; off = W1SZ; }
    else if (i < W1SZ + W2SZ + W3SZ)         { in = We3; out = oWe3; off = W1SZ + W2SZ; }
    else if (i < W1SZ + W2SZ + 2 * W3SZ)     { in = Wd1; out = oWd1; off = W1SZ + W2SZ + W3SZ; }
    else if (i < W1SZ + 2 * W2SZ + 2 * W3SZ) { in = Wd2; out = oWd2; off = W1SZ + W2SZ + 2 * W3SZ; }
    else                                     { in = Wd3; out = oWd3; off = W1SZ + 2 * W2SZ + 2 * W3SZ; }
    const long long k = i - off;
    float4 v0 = *(const float4*)(in + k);
    float4 v1 = *(const float4*)(in + k + 4);
    *(__nv_bfloat162*)(out + k)     = __floats2bfloat162_rn(v0.x, v0.y);
    *(__nv_bfloat162*)(out + k + 2) = __floats2bfloat162_rn(v0.z, v0.w);
    *(__nv_bfloat162*)(out + k + 4) = __floats2bfloat162_rn(v1.x, v1.y);
    *(__nv_bfloat162*)(out + k + 6) = __floats2bfloat162_rn(v1.z, v1.w);
}

// A1 = [dz(4096); z_c(128)] bf16 (K=32 rows), and zero the loss accumulator
__global__ void dz_k(const float* __restrict__ Z, bf16* __restrict__ A1,
                     float* __restrict__ loss)
{
    const int idx = blockIdx.x * 256 + threadIdx.x;   // < MENC*32
    if (idx == 0) *loss = 0.f;
    const int r = idx >> 5, j = idx & 31;
    float v;
    if (r < RTOT) v = Z[idx] - Z[(RTOT + (r >> 5)) * Z_DIM + j];
    else          v = Z[idx];
    A1[idx] = __float2bfloat16(v);
}

// E1: V1[r<4096] = t1 = 1[u_c+b>0] * u_nn ;  V1[4096+rc] = h1 = relu(u_c+b)
__global__ void eps1_k(const bf16* __restrict__ U1, const float* __restrict__ bd1,
                       bf16* __restrict__ V1)
{
    const long long i = (long long)(blockIdx.x * 256 + threadIdx.x) * 8;
    float un[8], uc[8], bv[8], o[8];
    if (i < (long long)RTOT * H_DIM) {
        const int r = (int)(i >> 10), j = (int)(i & 1023), b = r >> 5;
        unpack8(*(const uint4*)(U1 + (size_t)r * H_DIM + j), un);
        unpack8(*(const uint4*)(U1 + (size_t)(RTOT + b) * H_DIM + j), uc);
        *(float4*)bv = *(const float4*)(bd1 + j);
        *(float4*)(bv + 4) = *(const float4*)(bd1 + j + 4);
#pragma unroll
        for (int k = 0; k < 8; k++) o[k] = (uc[k] + bv[k] > 0.f) ? un[k] : 0.f;
        *(uint4*)(V1 + (size_t)r * H_DIM + j) = pack8(o);
    } else {
        const long long k2 = i - (long long)RTOT * H_DIM;
        const int rc = (int)(k2 >> 10), j = (int)(k2 & 1023);
        unpack8(*(const uint4*)(U1 + (size_t)(RTOT + rc) * H_DIM + j), uc);
        *(float4*)bv = *(const float4*)(bd1 + j);
        *(float4*)(bv + 4) = *(const float4*)(bd1 + j + 4);
#pragma unroll
        for (int k = 0; k < 8; k++) o[k] = fmaxf(uc[k] + bv[k], 0.f);
        *(uint4*)(V1 + (size_t)(RTOT + rc) * H_DIM + j) = pack8(o);
    }
}

// E2: S2[r] = u_c'>0 ? (u_c' + u_nn) : 0   where u_c' = U2_center + bd2
// (= h2 + t2: recon folded into the loss GEMM's A operand)
__global__ void eps2_k(const bf16* __restrict__ U2, const float* __restrict__ bd2,
                       bf16* __restrict__ S2)
{
    const long long i = (long long)(blockIdx.x * 256 + threadIdx.x) * 8;
    const int r = (int)(i >> 10), j = (int)(i & 1023), b = r >> 5;
    float un[8], uc[8], bv[8], o[8];
    unpack8(*(const uint4*)(U2 + (size_t)r * H_DIM + j), un);
    unpack8(*(const uint4*)(U2 + (size_t)(RTOT + b) * H_DIM + j), uc);
    *(float4*)bv = *(const float4*)(bd2 + j);
    *(float4*)(bv + 4) = *(const float4*)(bd2 + j + 4);
#pragma unroll
    for (int k = 0; k < 8; k++) {
        const float u = uc[k] + bv[k];
        o[k] = (u > 0.f) ? (u + un[k]) : 0.f;
    }
    *(uint4*)(S2 + (size_t)r * H_DIM + j) = pack8(o);
}

__global__ void final_k(const float* loss, float* out) { out[0] = *loss * (1.0f / (float)RTOT); }

// ---------------------------------------------------------------------------

extern "C" void kernel_launch(void* const* d_in, const int* in_sizes, int n_in,
                              void* d_out, int out_size)
{
    (void)in_sizes; (void)n_in; (void)out_size;
    const float* x_c  = (const float*)d_in[0];
    const float* x_nn = (const float*)d_in[1];
    const float* We1  = (const float*)d_in[2];
    const float* be1  = (const float*)d_in[3];
    const float* We2  = (const float*)d_in[4];
    const float* be2  = (const float*)d_in[5];
    const float* We3  = (const float*)d_in[6];
    const float* be3  = (const float*)d_in[7];
    const float* Wd1  = (const float*)d_in[8];
    const float* bd1  = (const float*)d_in[9];
    const float* Wd2  = (const float*)d_in[10];
    const float* bd2  = (const float*)d_in[11];
    const float* Wd3  = (const float*)d_in[12];
    const float* bd3  = (const float*)d_in[13];
    float* out = (float*)d_out;

    bf16 *Abf, *We1b, *We2b, *We3b, *Wd1b, *Wd2b, *Wd3b;
    bf16 *H1b, *H2b, *A1, *U1, *V1, *U2, *S2;
    float *Z, *w, *loss;
    cudaGetSymbolAddress((void**)&Abf,  g_Abf);
    cudaGetSymbolAddress((void**)&We1b, g_We1b);
    cudaGetSymbolAddress((void**)&We2b, g_We2b);
    cudaGetSymbolAddress((void**)&We3b, g_We3b);
    cudaGetSymbolAddress((void**)&Wd1b, g_Wd1b);
    cudaGetSymbolAddress((void**)&Wd2b, g_Wd2b);
    cudaGetSymbolAddress((void**)&Wd3b, g_Wd3b);
    cudaGetSymbolAddress((void**)&H1b,  g_H1b);
    cudaGetSymbolAddress((void**)&H2b,  g_H2b);
    cudaGetSymbolAddress((void**)&Z,    g_Z);
    cudaGetSymbolAddress((void**)&A1,   g_A1);
    cudaGetSymbolAddress((void**)&U1,   g_U1);
    cudaGetSymbolAddress((void**)&V1,   g_V1);
    cudaGetSymbolAddress((void**)&U2,   g_U2);
    cudaGetSymbolAddress((void**)&S2,   g_S2);
    cudaGetSymbolAddress((void**)&w,    g_w);
    cudaGetSymbolAddress((void**)&loss, g_loss);

    cudaFuncSetAttribute(mma_gemm<EPI_BIAS_RELU_BF>, cudaFuncAttributeMaxDynamicSharedMemorySize, SMEM_DYN);
    cudaFuncSetAttribute(mma_gemm<EPI_NONE_BF>,      cudaFuncAttributeMaxDynamicSharedMemorySize, SMEM_DYN);
    cudaFuncSetAttribute(mma_gemm<EPI_LOSS>,         cudaFuncAttributeMaxDynamicSharedMemorySize, SMEM_DYN);

    const dim3 blk(256);
    auto ggrid = [](int M, int N) { return dim3(N / 128, M / 128); };

    // prologue conversions
    xconv_k<<<MENC, blk>>>(x_nn, x_c, Abf, w);
    wconv_k<<<(WTOT / 8 + 255) / 256, blk>>>(We1, We2, We3, Wd1, Wd2, Wd3,
                                             We1b, We2b, We3b, Wd1b, Wd2b, Wd3b);

    // encoder (x_nn ++ x_c merged, M = 4224)
    mma_gemm<EPI_BIAS_RELU_BF><<<ggrid(MENC, H_DIM), blk, SMEM_DYN>>>(
        Abf, We1b, H1b, MENC, H_DIM, D_DIM, be1, nullptr, nullptr, nullptr);
    mma_gemm<EPI_BIAS_RELU_BF><<<ggrid(MENC, H_DIM), blk, SMEM_DYN>>>(
        H1b, We2b, H2b, MENC, H_DIM, H_DIM, be2, nullptr, nullptr, nullptr);
    gemm_n32_bf<<<MENC / 8, blk>>>(H2b, We3b, be3, Z, H_DIM);

    // A1 = [dz; z_c] (+ loss zero)
    dz_k<<<(MENC * Z_DIM) / 256, blk>>>(Z, A1, loss);

    // merged decoder+JVP chain (center rows ride along; hess == 0 for ReLU MLP)
    mma_gemm<EPI_NONE_BF><<<ggrid(MENC, H_DIM), blk, SMEM_DYN>>>(
        A1, Wd1b, U1, MENC, H_DIM, Z_DIM, nullptr, nullptr, nullptr, nullptr);
    eps1_k<<<(MENC * H_DIM) / (256 * 8), blk>>>(U1, bd1, V1);
    mma_gemm<EPI_NONE_BF><<<ggrid(MENC, H_DIM), blk, SMEM_DYN>>>(
        V1, Wd2b, U2, MENC, H_DIM, H_DIM, nullptr, nullptr, nullptr, nullptr);
    eps2_k<<<(RTOT * H_DIM) / (256 * 8), blk>>>(U2, bd2, S2);

    // loss GEMM: diff = x_nn - (S2 @ Wd3 + bd3); recon folded into S2
    mma_gemm<EPI_LOSS><<<ggrid(RTOT, D_DIM), blk, SMEM_DYN>>>(
        S2, Wd3b, nullptr, RTOT, D_DIM, H_DIM, bd3, x_nn, w, loss);

    final_k<<<1, 1>>>(loss, out);
}